// round 3
// baseline (speedup 1.0000x reference)
#include <cuda_runtime.h>
#include <cuda_fp16.h>
#include <cstdint>

#define DI __device__ __forceinline__

// ---------------- persistent prepped weights ----------------
__device__ __half g_W1h[384 * 256];   // [theta;phi;g] rows j, cols c (fp16 hi)
__device__ __half g_W1l[384 * 256];   // fp16 lo part
__device__ __half g_Wwh[256 * 128];   // w_w * bn_scale, rows c, cols i
__device__ float  g_b1[384];          // [theta_b; phi_b; g_b]
__device__ float  g_b2[256];          // w_b*scale + bn_beta

__global__ void prep_kernel(const float* __restrict__ tw, const float* __restrict__ tb,
                            const float* __restrict__ pw, const float* __restrict__ pb,
                            const float* __restrict__ gw, const float* __restrict__ gb,
                            const float* __restrict__ ww, const float* __restrict__ wb,
                            const float* __restrict__ gamma, const float* __restrict__ beta) {
    int idx = blockIdx.x * blockDim.x + threadIdx.x;
    const float inv = rsqrtf(1.0f + 1e-5f);
    if (idx < 384 * 256) {
        int j = idx >> 8, c = idx & 255;
        float v = (j < 128) ? tw[j * 256 + c]
                : (j < 256) ? pw[(j - 128) * 256 + c]
                            : gw[(j - 256) * 256 + c];
        __half h = __float2half_rn(v);
        g_W1h[idx] = h;
        g_W1l[idx] = __float2half_rn(v - __half2float(h));
    }
    if (idx < 256 * 128) {
        int c = idx >> 7;
        g_Wwh[idx] = __float2half_rn(ww[idx] * (gamma[c] * inv));
    }
    if (idx < 384) g_b1[idx] = (idx < 128) ? tb[idx] : ((idx < 256) ? pb[idx - 128] : gb[idx - 256]);
    if (idx < 256) g_b2[idx] = wb[idx] * (gamma[idx] * inv) + beta[idx];
}

// ---------------- helpers ----------------
DI uint32_t packh2(float a, float b) {
    __half2 h = __halves2half2(__float2half_rn(a), __float2half_rn(b));
    return *reinterpret_cast<uint32_t*>(&h);
}
DI void split2(float a, float b, uint32_t& hi, uint32_t& lo) {
    __half ha = __float2half_rn(a), hb = __float2half_rn(b);
    float la = a - __half2float(ha), lb = b - __half2float(hb);
    __half2 H = __halves2half2(ha, hb);
    hi = *reinterpret_cast<uint32_t*>(&H);
    lo = packh2(la, lb);
}
DI void ldm4(uint32_t* r, uint32_t addr) {
    asm volatile("ldmatrix.sync.aligned.m8n8.x4.shared.b16 {%0,%1,%2,%3}, [%4];\n"
                 : "=r"(r[0]), "=r"(r[1]), "=r"(r[2]), "=r"(r[3]) : "r"(addr));
}
DI void mma16816(float* d, const uint32_t* a, uint32_t b0, uint32_t b1) {
    asm volatile("mma.sync.aligned.m16n8k16.row.col.f32.f16.f16.f32 "
                 "{%0,%1,%2,%3}, {%4,%5,%6,%7}, {%8,%9}, {%0,%1,%2,%3};\n"
                 : "+f"(d[0]), "+f"(d[1]), "+f"(d[2]), "+f"(d[3])
                 : "r"(a[0]), "r"(a[1]), "r"(a[2]), "r"(a[3]), "r"(b0), "r"(b1));
}
DI float hmax4(float a, float b, float c, float d) { return fmaxf(fmaxf(a, b), fmaxf(c, d)); }

// ---------------- smem layout (bytes) ----------------
constexpr int OFF_XH = 0;        // half [64][256] swizzled (32 chunks/row)
constexpr int OFF_XL = 32768;    // half [64][256]
constexpr int OFF_TH = 65536;    // half [64][128] swizzled (theta hi)
constexpr int OFF_TL = 81920;    // theta lo
constexpr int OFF_YB = 98304;    // half [64][128] swizzled (y)
constexpr int OFF_PH = 114688;   // half [16][136] phi pooled hi
constexpr int OFF_PL = 119040;   // phi pooled lo
constexpr int OFF_GX = 123392;   // half [128][16] gx pooled (i-major)
constexpr int OFF_B1 = 127488;   // float[384]
constexpr int OFF_B2 = 129024;   // float[256]
constexpr int OFF_GO = 130048;   // int[64]
constexpr int SMEM_BYTES = 130304;

__global__ void __launch_bounds__(256, 1)
nl_kernel(const float* __restrict__ x, const int* __restrict__ grouped,
          float* __restrict__ out) {
    extern __shared__ char smem[];
    const uint32_t sbase = (uint32_t)__cvta_generic_to_shared(smem);
    float* b1s = (float*)(smem + OFF_B1);
    float* b2s = (float*)(smem + OFF_B2);
    int*   gos = (int*)(smem + OFF_GO);

    const int tid = threadIdx.x, warp = tid >> 5, lane = tid & 31;
    const int g = lane >> 2, t = lane & 3;
    const int blk = blockIdx.x;

    // ---- phase 0: tables ----
    if (tid < 64) gos[tid] = grouped[tid];
    if (tid < 256) { b2s[tid] = g_b2[tid]; b1s[tid] = g_b1[tid]; }
    if (tid < 128) b1s[256 + tid] = g_b1[256 + tid];
    __syncthreads();

    // ---- phase 1: gather rows by grouped order, split to fp16 hi/lo, swizzled ----
    {
        const float4* x4 = (const float4*)x;
        uint4* XH4 = (uint4*)(smem + OFF_XH);
        uint4* XL4 = (uint4*)(smem + OFF_XL);
#pragma unroll
        for (int it = 0; it < 8; it++) {
            int ci = tid + it * 256;            // 0..2047 : 64 rows x 32 chunks
            int r = ci >> 5, ch = ci & 31;
            size_t rb = ((size_t)blk * 64 + gos[r]) * 64;
            float4 va = x4[rb + ch * 2];
            float4 vb = x4[rb + ch * 2 + 1];
            float f[8] = {va.x, va.y, va.z, va.w, vb.x, vb.y, vb.z, vb.w};
            uint32_t hw[4], lw[4];
#pragma unroll
            for (int q = 0; q < 4; q++) split2(f[2 * q], f[2 * q + 1], hw[q], lw[q]);
            int pos = r * 32 + (ch ^ (r & 7));
            XH4[pos] = make_uint4(hw[0], hw[1], hw[2], hw[3]);
            XL4[pos] = make_uint4(lw[0], lw[1], lw[2], lw[3]);
        }
    }
    __syncthreads();

    // ---- phase 2: GEMM1  Out1[64][384] = Xg @ W1^T ----
    // theta/phi (j 0..255): 3-pass split; g (j 256..383): 1-pass
    float accA[4][4][4];  // [m-tile][n-tile][4] theta/phi, cols warp*32 + b*8
    float accG[4][2][4];  // g, cols 256 + warp*16 + b*8
#pragma unroll
    for (int a_ = 0; a_ < 4; a_++)
#pragma unroll
        for (int b_ = 0; b_ < 4; b_++)
#pragma unroll
            for (int c_ = 0; c_ < 4; c_++) {
                accA[a_][b_][c_] = 0.f;
                if (b_ < 2) accG[a_][b_][c_] = 0.f;
            }
    const int colA = warp * 32;
    const int colG = 256 + warp * 16;

    for (int ks = 0; ks < 16; ks++) {
        uint32_t ah[4][4], al[4][4];
        int rr = lane & 15, hk = lane >> 4;
#pragma unroll
        for (int mt = 0; mt < 4; mt++) {
            int r = mt * 16 + rr, ch = ks * 2 + hk;
            uint32_t off = r * 512 + ((ch ^ (r & 7)) << 4);
            ldm4(ah[mt], sbase + OFF_XH + off);
            ldm4(al[mt], sbase + OFF_XL + off);
        }
#pragma unroll
        for (int b_ = 0; b_ < 4; b_++) {
            int j = colA + b_ * 8 + g;
            const __half* ph = g_W1h + j * 256 + ks * 16 + t * 2;
            const __half* pl = g_W1l + j * 256 + ks * 16 + t * 2;
            uint32_t bh0 = *(const uint32_t*)ph, bh1 = *(const uint32_t*)(ph + 8);
            uint32_t bl0 = *(const uint32_t*)pl, bl1 = *(const uint32_t*)(pl + 8);
#pragma unroll
            for (int mt = 0; mt < 4; mt++) {
                mma16816(accA[mt][b_], ah[mt], bh0, bh1);
                mma16816(accA[mt][b_], al[mt], bh0, bh1);
                mma16816(accA[mt][b_], ah[mt], bl0, bl1);
            }
        }
#pragma unroll
        for (int b_ = 0; b_ < 2; b_++) {
            int j = colG + b_ * 8 + g;
            const __half* ph = g_W1h + j * 256 + ks * 16 + t * 2;
            uint32_t bh0 = *(const uint32_t*)ph, bh1 = *(const uint32_t*)(ph + 8);
#pragma unroll
            for (int mt = 0; mt < 4; mt++) mma16816(accG[mt][b_], ah[mt], bh0, bh1);
        }
    }

    // ---- GEMM1 epilogue: theta store (warps 0-3), phi pool+store (warps 4-7), g pool+store (all) ----
    {
        uint32_t* TH = (uint32_t*)(smem + OFF_TH);
        uint32_t* TL = (uint32_t*)(smem + OFF_TL);
        uint32_t* PH = (uint32_t*)(smem + OFF_PH);
        uint32_t* PL = (uint32_t*)(smem + OFF_PL);
        __half*   GX = (__half*)(smem + OFF_GX);
#pragma unroll
        for (int b_ = 0; b_ < 4; b_++) {
            int c = colA + b_ * 8 + t * 2;
            float bi0 = b1s[c], bi1 = b1s[c + 1];
#pragma unroll
            for (int mt = 0; mt < 4; mt++) {
                float v00 = accA[mt][b_][0] + bi0, v01 = accA[mt][b_][1] + bi1;
                float v10 = accA[mt][b_][2] + bi0, v11 = accA[mt][b_][3] + bi1;
                if (warp < 4) {
                    // theta: i = c (0..127), rows r0,r0+8
                    int r0 = mt * 16 + g, r1 = r0 + 8;
                    int wd = c >> 1, chn = c >> 3;
                    uint32_t hi, lo;
                    split2(v00, v01, hi, lo);
                    int p0 = (((chn ^ (r0 & 7)) << 2) | (wd & 3));
                    TH[r0 * 64 + p0] = hi; TL[r0 * 64 + p0] = lo;
                    split2(v10, v11, hi, lo);
                    int p1 = (((chn ^ (r1 & 7)) << 2) | (wd & 3));
                    TH[r1 * 64 + p1] = hi; TL[r1 * 64 + p1] = lo;
                } else {
                    // phi: pool over groups of 4 sequence rows via shfl
                    v00 = fmaxf(v00, __shfl_xor_sync(0xffffffffu, v00, 4));
                    v00 = fmaxf(v00, __shfl_xor_sync(0xffffffffu, v00, 8));
                    v01 = fmaxf(v01, __shfl_xor_sync(0xffffffffu, v01, 4));
                    v01 = fmaxf(v01, __shfl_xor_sync(0xffffffffu, v01, 8));
                    v10 = fmaxf(v10, __shfl_xor_sync(0xffffffffu, v10, 4));
                    v10 = fmaxf(v10, __shfl_xor_sync(0xffffffffu, v10, 8));
                    v11 = fmaxf(v11, __shfl_xor_sync(0xffffffffu, v11, 4));
                    v11 = fmaxf(v11, __shfl_xor_sync(0xffffffffu, v11, 8));
                    if ((g & 3) == 0) {
                        int i = c - 128;
                        int p01 = mt * 4 + (g >> 2), p23 = p01 + 2;
                        uint32_t hi, lo;
                        split2(v00, v01, hi, lo);
                        PH[p01 * 68 + (i >> 1)] = hi; PL[p01 * 68 + (i >> 1)] = lo;
                        split2(v10, v11, hi, lo);
                        PH[p23 * 68 + (i >> 1)] = hi; PL[p23 * 68 + (i >> 1)] = lo;
                    }
                }
            }
        }
        // g pooled -> GX[i][p] (all warps)
#pragma unroll
        for (int b_ = 0; b_ < 2; b_++) {
            int c = colG + b_ * 8 + t * 2;
            int i = c - 256;
            float bi0 = b1s[c], bi1 = b1s[c + 1];
#pragma unroll
            for (int mt = 0; mt < 4; mt++) {
                float v00 = accG[mt][b_][0] + bi0, v01 = accG[mt][b_][1] + bi1;
                float v10 = accG[mt][b_][2] + bi0, v11 = accG[mt][b_][3] + bi1;
                v00 = fmaxf(v00, __shfl_xor_sync(0xffffffffu, v00, 4));
                v00 = fmaxf(v00, __shfl_xor_sync(0xffffffffu, v00, 8));
                v01 = fmaxf(v01, __shfl_xor_sync(0xffffffffu, v01, 4));
                v01 = fmaxf(v01, __shfl_xor_sync(0xffffffffu, v01, 8));
                v10 = fmaxf(v10, __shfl_xor_sync(0xffffffffu, v10, 4));
                v10 = fmaxf(v10, __shfl_xor_sync(0xffffffffu, v10, 8));
                v11 = fmaxf(v11, __shfl_xor_sync(0xffffffffu, v11, 4));
                v11 = fmaxf(v11, __shfl_xor_sync(0xffffffffu, v11, 8));
                if ((g & 3) == 0) {
                    int p01 = mt * 4 + (g >> 2), p23 = p01 + 2;
                    GX[i * 16 + p01]       = __float2half_rn(v00);
                    GX[(i + 1) * 16 + p01] = __float2half_rn(v01);
                    GX[i * 16 + p23]       = __float2half_rn(v10);
                    GX[(i + 1) * 16 + p23] = __float2half_rn(v11);
                }
            }
        }
    }
    __syncthreads();

    // ---- phase 3 (warps 0-3): f = theta @ phiP^T (3-pass), softmax, y = a @ gx ----
    if (warp < 4) {
        float accF[2][4];
#pragma unroll
        for (int n_ = 0; n_ < 2; n_++)
#pragma unroll
            for (int c_ = 0; c_ < 4; c_++) accF[n_][c_] = 0.f;

        const __half* PHh = (const __half*)(smem + OFF_PH);
        const __half* PLh = (const __half*)(smem + OFF_PL);
        for (int ks = 0; ks < 8; ks++) {
            uint32_t th[4], tl[4];
            int r = warp * 16 + (lane & 15), ch = ks * 2 + (lane >> 4);
            uint32_t off = r * 256 + ((ch ^ (r & 7)) << 4);
            ldm4(th, sbase + OFF_TH + off);
            ldm4(tl, sbase + OFF_TL + off);
#pragma unroll
            for (int n_ = 0; n_ < 2; n_++) {
                int m = n_ * 8 + g;
                const uint32_t* bh = (const uint32_t*)(PHh + m * 136 + ks * 16 + t * 2);
                const uint32_t* bl = (const uint32_t*)(PLh + m * 136 + ks * 16 + t * 2);
                uint32_t bh0 = bh[0], bh1 = bh[4], bl0 = bl[0], bl1 = bl[4];
                mma16816(accF[n_], th, bh0, bh1);
                mma16816(accF[n_], tl, bh0, bh1);
                mma16816(accF[n_], th, bl0, bl1);
            }
        }
        // softmax over the 16 m-columns; row A = warp*16+g, row B = +8
        float a0 = accF[0][0], a1 = accF[0][1], a2 = accF[1][0], a3 = accF[1][1];
        float c0 = accF[0][2], c1 = accF[0][3], c2 = accF[1][2], c3 = accF[1][3];
        float mA = hmax4(a0, a1, a2, a3), mB = hmax4(c0, c1, c2, c3);
        mA = fmaxf(mA, __shfl_xor_sync(0xffffffffu, mA, 1));
        mA = fmaxf(mA, __shfl_xor_sync(0xffffffffu, mA, 2));
        mB = fmaxf(mB, __shfl_xor_sync(0xffffffffu, mB, 1));
        mB = fmaxf(mB, __shfl_xor_sync(0xffffffffu, mB, 2));
        a0 = __expf(a0 - mA); a1 = __expf(a1 - mA); a2 = __expf(a2 - mA); a3 = __expf(a3 - mA);
        c0 = __expf(c0 - mB); c1 = __expf(c1 - mB); c2 = __expf(c2 - mB); c3 = __expf(c3 - mB);
        float sA = a0 + a1 + a2 + a3, sB = c0 + c1 + c2 + c3;
        sA += __shfl_xor_sync(0xffffffffu, sA, 1);
        sA += __shfl_xor_sync(0xffffffffu, sA, 2);
        sB += __shfl_xor_sync(0xffffffffu, sB, 1);
        sB += __shfl_xor_sync(0xffffffffu, sB, 2);
        float iA = 1.0f / sA, iB = 1.0f / sB;
        a0 *= iA; a1 *= iA; a2 *= iA; a3 *= iA;
        c0 *= iB; c1 *= iB; c2 *= iB; c3 *= iB;
        uint32_t fa[4];
        fa[0] = packh2(a0, a1); fa[1] = packh2(c0, c1);
        fa[2] = packh2(a2, a3); fa[3] = packh2(c2, c3);

        // y[64][128] = a[64][16] @ gxp  (K=16, 1 k-step)
        float accY[16][4];
#pragma unroll
        for (int nt = 0; nt < 16; nt++)
#pragma unroll
            for (int c_ = 0; c_ < 4; c_++) accY[nt][c_] = 0.f;
        const __half* GX = (const __half*)(smem + OFF_GX);
#pragma unroll
        for (int nt = 0; nt < 16; nt++) {
            int irow = nt * 8 + g;
            const uint32_t* bp = (const uint32_t*)(GX + irow * 16 + t * 2);
            mma16816(accY[nt], fa, bp[0], bp[4]);
        }
        // store y as fp16 swizzled
        uint32_t* YB = (uint32_t*)(smem + OFF_YB);
        int r0 = warp * 16 + g, r1 = r0 + 8;
#pragma unroll
        for (int nt = 0; nt < 16; nt++) {
            YB[r0 * 64 + (((nt ^ (r0 & 7)) << 2) | t)] = packh2(accY[nt][0], accY[nt][1]);
            YB[r1 * 64 + (((nt ^ (r1 & 7)) << 2) | t)] = packh2(accY[nt][2], accY[nt][3]);
        }
    }
    __syncthreads();

    // ---- phase 4: wy[64][256] = y @ Ww^T (1-pass), + bias + residual, scatter ----
    float accW[4][4][4];
#pragma unroll
    for (int a_ = 0; a_ < 4; a_++)
#pragma unroll
        for (int b_ = 0; b_ < 4; b_++)
#pragma unroll
            for (int c_ = 0; c_ < 4; c_++) accW[a_][b_][c_] = 0.f;

    for (int ks = 0; ks < 8; ks++) {
        uint32_t ya[4][4];
        int rr = lane & 15, hk = lane >> 4;
#pragma unroll
        for (int mt = 0; mt < 4; mt++) {
            int r = mt * 16 + rr, ch = ks * 2 + hk;
            ldm4(ya[mt], sbase + OFF_YB + r * 256 + ((ch ^ (r & 7)) << 4));
        }
#pragma unroll
        for (int b_ = 0; b_ < 4; b_++) {
            int j = warp * 32 + b_ * 8 + g;  // output channel c
            const __half* p = g_Wwh + j * 128 + ks * 16 + t * 2;
            uint32_t w0 = *(const uint32_t*)p, w1 = *(const uint32_t*)(p + 8);
#pragma unroll
            for (int mt = 0; mt < 4; mt++) mma16816(accW[mt][b_], ya[mt], w0, w1);
        }
    }

    {
        const uint32_t* XHw = (const uint32_t*)(smem + OFF_XH);
        const uint32_t* XLw = (const uint32_t*)(smem + OFF_XL);
#pragma unroll
        for (int b_ = 0; b_ < 4; b_++) {
            int c = warp * 32 + b_ * 8 + t * 2;
            float bi0 = b2s[c], bi1 = b2s[c + 1];
            int chn = c >> 3, wdm = (c >> 1) & 3;
#pragma unroll
            for (int mt = 0; mt < 4; mt++) {
#pragma unroll
                for (int h_ = 0; h_ < 2; h_++) {
                    int r = mt * 16 + g + h_ * 8;
                    int pos = r * 128 + (((chn ^ (r & 7)) << 2) | wdm);
                    uint32_t xh = XHw[pos], xl = XLw[pos];
                    __half2 H = *reinterpret_cast<__half2*>(&xh);
                    __half2 L = *reinterpret_cast<__half2*>(&xl);
                    float o0 = accW[mt][b_][h_ * 2 + 0] + bi0 + __low2float(H) + __low2float(L);
                    float o1 = accW[mt][b_][h_ * 2 + 1] + bi1 + __high2float(H) + __high2float(L);
                    float2* dst = (float2*)(out + ((size_t)blk * 64 + gos[r]) * 256 + c);
                    *dst = make_float2(o0, o1);
                }
            }
        }
    }
}

extern "C" void kernel_launch(void* const* d_in, const int* in_sizes, int n_in,
                              void* d_out, int out_size) {
    const float* x       = (const float*)d_in[0];
    const int*   grouped = (const int*)d_in[1];
    const float* tw  = (const float*)d_in[3];
    const float* tb  = (const float*)d_in[4];
    const float* pw  = (const float*)d_in[5];
    const float* pb  = (const float*)d_in[6];
    const float* gw  = (const float*)d_in[7];
    const float* gb  = (const float*)d_in[8];
    const float* ww  = (const float*)d_in[9];
    const float* wb  = (const float*)d_in[10];
    const float* gam = (const float*)d_in[11];
    const float* bet = (const float*)d_in[12];
    float* out = (float*)d_out;

    prep_kernel<<<384, 256>>>(tw, tb, pw, pb, gw, gb, ww, wb, gam, bet);
    cudaFuncSetAttribute(nl_kernel, cudaFuncAttributeMaxDynamicSharedMemorySize, SMEM_BYTES);
    nl_kernel<<<4096, 256, SMEM_BYTES>>>(x, grouped, out);
}

// round 4
// speedup vs baseline: 1.2663x; 1.2663x over previous
#include <cuda_runtime.h>
#include <cuda_fp16.h>
#include <cstdint>

#define DI __device__ __forceinline__

// ---------------- persistent prepped weights ----------------
__device__ __half g_W1h[384 * 256];   // [theta;phi;g] rows j, cols c (fp16)
__device__ __half g_Wwh[256 * 128];   // w_w * bn_scale, rows c, cols i
__device__ float  g_b1[384];          // [theta_b; phi_b; g_b]
__device__ float  g_b2[256];          // w_b*scale + bn_beta

__global__ void prep_kernel(const float* __restrict__ tw, const float* __restrict__ tb,
                            const float* __restrict__ pw, const float* __restrict__ pb,
                            const float* __restrict__ gw, const float* __restrict__ gb,
                            const float* __restrict__ ww, const float* __restrict__ wb,
                            const float* __restrict__ gamma, const float* __restrict__ beta) {
    int idx = blockIdx.x * blockDim.x + threadIdx.x;
    const float inv = rsqrtf(1.0f + 1e-5f);
    if (idx < 384 * 256) {
        int j = idx >> 8, c = idx & 255;
        float v = (j < 128) ? tw[j * 256 + c]
                : (j < 256) ? pw[(j - 128) * 256 + c]
                            : gw[(j - 256) * 256 + c];
        g_W1h[idx] = __float2half_rn(v);
    }
    if (idx < 256 * 128) {
        int c = idx >> 7;
        g_Wwh[idx] = __float2half_rn(ww[idx] * (gamma[c] * inv));
    }
    if (idx < 384) g_b1[idx] = (idx < 128) ? tb[idx] : ((idx < 256) ? pb[idx - 128] : gb[idx - 256]);
    if (idx < 256) g_b2[idx] = wb[idx] * (gamma[idx] * inv) + beta[idx];
}

// ---------------- helpers ----------------
DI uint32_t packh2(float a, float b) {
    __half2 h = __halves2half2(__float2half_rn(a), __float2half_rn(b));
    return *reinterpret_cast<uint32_t*>(&h);
}
DI void ldm4(uint32_t* r, uint32_t addr) {
    asm volatile("ldmatrix.sync.aligned.m8n8.x4.shared.b16 {%0,%1,%2,%3}, [%4];\n"
                 : "=r"(r[0]), "=r"(r[1]), "=r"(r[2]), "=r"(r[3]) : "r"(addr));
}
DI void mma16816(float* d, const uint32_t* a, uint32_t b0, uint32_t b1) {
    asm volatile("mma.sync.aligned.m16n8k16.row.col.f32.f16.f16.f32 "
                 "{%0,%1,%2,%3}, {%4,%5,%6,%7}, {%8,%9}, {%0,%1,%2,%3};\n"
                 : "+f"(d[0]), "+f"(d[1]), "+f"(d[2]), "+f"(d[3])
                 : "r"(a[0]), "r"(a[1]), "r"(a[2]), "r"(a[3]), "r"(b0), "r"(b1));
}
DI float hmax4(float a, float b, float c, float d) { return fmaxf(fmaxf(a, b), fmaxf(c, d)); }

// ---------------- smem layout (bytes) ----------------
constexpr int XF_STRIDE = 260;   // floats per row; 260*4 mod 128 = 16 -> conflict-free rows
constexpr int OFF_XF = 0;        // f32 [64][260] gathered x (exact residual)   66560 B
constexpr int OFF_XH = 66560;    // half [64][256] swizzled (GEMM1 A)           32768 B
constexpr int OFF_TH = 99328;    // half [64][128] swizzled (theta)             16384 B
constexpr int OFF_YB = 115712;   // half [64][128] swizzled (y)                 16384 B
constexpr int OFF_PH = 132096;   // half [16][136] phi pooled                    4352 B
constexpr int OFF_GX = 136448;   // half [128][16] gx pooled (i-major)           4096 B
constexpr int OFF_B1 = 140544;   // float[384]
constexpr int OFF_B2 = 142080;   // float[256]
constexpr int OFF_GO = 143104;   // int[64]
constexpr int SMEM_BYTES = 143360;

__global__ void __launch_bounds__(256, 1)
nl_kernel(const float* __restrict__ x, const int* __restrict__ grouped,
          float* __restrict__ out) {
    extern __shared__ char smem[];
    const uint32_t sbase = (uint32_t)__cvta_generic_to_shared(smem);
    float* XF  = (float*)(smem + OFF_XF);
    float* b1s = (float*)(smem + OFF_B1);
    float* b2s = (float*)(smem + OFF_B2);
    int*   gos = (int*)(smem + OFF_GO);

    const int tid = threadIdx.x, warp = tid >> 5, lane = tid & 31;
    const int g = lane >> 2, t = lane & 3;
    const int blk = blockIdx.x;

    // ---- phase 0: tables ----
    if (tid < 64) gos[tid] = grouped[tid];
    b2s[tid] = g_b2[tid];
    b1s[tid] = g_b1[tid];
    if (tid < 128) b1s[256 + tid] = g_b1[256 + tid];
    __syncthreads();

    // ---- phase 1: gather rows by grouped order; fp32 copy + fp16 swizzled copy ----
    {
        const float4* x4 = (const float4*)x;
        uint4* XH4 = (uint4*)(smem + OFF_XH);
#pragma unroll
        for (int it = 0; it < 8; it++) {
            int ci = tid + it * 256;            // 0..2047 : 64 rows x 32 chunks of 8 floats
            int r = ci >> 5, ch = ci & 31;
            size_t rb = ((size_t)blk * 64 + gos[r]) * 64;
            float4 va = x4[rb + ch * 2];
            float4 vb = x4[rb + ch * 2 + 1];
            // fp32 residual copy
            float4* xf4 = (float4*)(XF + r * XF_STRIDE + ch * 8);
            xf4[0] = va; xf4[1] = vb;
            // fp16 swizzled copy
            uint4 w;
            w.x = packh2(va.x, va.y); w.y = packh2(va.z, va.w);
            w.z = packh2(vb.x, vb.y); w.w = packh2(vb.z, vb.w);
            XH4[r * 32 + (ch ^ (r & 7))] = w;
        }
    }
    __syncthreads();

    // ---- phase 2: GEMM1  Out1[64][384] = Xg @ W1^T (single-pass fp16) ----
    float accA[4][4][4];  // theta/phi: cols warp*32 + b_*8
    float accG[4][2][4];  // g: cols 256 + warp*16 + b_*8
#pragma unroll
    for (int a_ = 0; a_ < 4; a_++)
#pragma unroll
        for (int b_ = 0; b_ < 4; b_++)
#pragma unroll
            for (int c_ = 0; c_ < 4; c_++) {
                accA[a_][b_][c_] = 0.f;
                if (b_ < 2) accG[a_][b_][c_] = 0.f;
            }
    const int colA = warp * 32;
    const int colG = 256 + warp * 16;

    for (int ks = 0; ks < 16; ks++) {
        uint32_t ah[4][4];
        int rr = lane & 15, hk = lane >> 4;
#pragma unroll
        for (int mt = 0; mt < 4; mt++) {
            int r = mt * 16 + rr, ch = ks * 2 + hk;
            ldm4(ah[mt], sbase + OFF_XH + r * 512 + ((ch ^ (r & 7)) << 4));
        }
#pragma unroll
        for (int b_ = 0; b_ < 4; b_++) {
            int j = colA + b_ * 8 + g;
            const __half* ph = g_W1h + j * 256 + ks * 16 + t * 2;
            uint32_t bh0 = *(const uint32_t*)ph, bh1 = *(const uint32_t*)(ph + 8);
#pragma unroll
            for (int mt = 0; mt < 4; mt++) mma16816(accA[mt][b_], ah[mt], bh0, bh1);
        }
#pragma unroll
        for (int b_ = 0; b_ < 2; b_++) {
            int j = colG + b_ * 8 + g;
            const __half* ph = g_W1h + j * 256 + ks * 16 + t * 2;
            uint32_t bh0 = *(const uint32_t*)ph, bh1 = *(const uint32_t*)(ph + 8);
#pragma unroll
            for (int mt = 0; mt < 4; mt++) mma16816(accG[mt][b_], ah[mt], bh0, bh1);
        }
    }

    // ---- GEMM1 epilogue: theta store (warps 0-3), phi pool+store (warps 4-7), g pool (all) ----
    {
        uint32_t* TH = (uint32_t*)(smem + OFF_TH);
        uint32_t* PH = (uint32_t*)(smem + OFF_PH);
        __half*   GX = (__half*)(smem + OFF_GX);
#pragma unroll
        for (int b_ = 0; b_ < 4; b_++) {
            int c = colA + b_ * 8 + t * 2;
            float bi0 = b1s[c], bi1 = b1s[c + 1];
#pragma unroll
            for (int mt = 0; mt < 4; mt++) {
                float v00 = accA[mt][b_][0] + bi0, v01 = accA[mt][b_][1] + bi1;
                float v10 = accA[mt][b_][2] + bi0, v11 = accA[mt][b_][3] + bi1;
                if (warp < 4) {
                    // theta: i = c (0..127), rows r0, r0+8
                    int r0 = mt * 16 + g, r1 = r0 + 8;
                    int wd = c >> 1, chn = c >> 3;
                    int p0 = (((chn ^ (r0 & 7)) << 2) | (wd & 3));
                    TH[r0 * 64 + p0] = packh2(v00, v01);
                    int p1 = (((chn ^ (r1 & 7)) << 2) | (wd & 3));
                    TH[r1 * 64 + p1] = packh2(v10, v11);
                } else {
                    // phi: max-pool groups of 4 sequence rows via shfl
                    v00 = fmaxf(v00, __shfl_xor_sync(0xffffffffu, v00, 4));
                    v00 = fmaxf(v00, __shfl_xor_sync(0xffffffffu, v00, 8));
                    v01 = fmaxf(v01, __shfl_xor_sync(0xffffffffu, v01, 4));
                    v01 = fmaxf(v01, __shfl_xor_sync(0xffffffffu, v01, 8));
                    v10 = fmaxf(v10, __shfl_xor_sync(0xffffffffu, v10, 4));
                    v10 = fmaxf(v10, __shfl_xor_sync(0xffffffffu, v10, 8));
                    v11 = fmaxf(v11, __shfl_xor_sync(0xffffffffu, v11, 4));
                    v11 = fmaxf(v11, __shfl_xor_sync(0xffffffffu, v11, 8));
                    if ((g & 3) == 0) {
                        int i = c - 128;
                        int p01 = mt * 4 + (g >> 2), p23 = p01 + 2;
                        PH[p01 * 68 + (i >> 1)] = packh2(v00, v01);
                        PH[p23 * 68 + (i >> 1)] = packh2(v10, v11);
                    }
                }
            }
        }
        // g pooled -> GX[i][p] (all warps)
#pragma unroll
        for (int b_ = 0; b_ < 2; b_++) {
            int c = colG + b_ * 8 + t * 2;
            int i = c - 256;
            float bi0 = b1s[c], bi1 = b1s[c + 1];
#pragma unroll
            for (int mt = 0; mt < 4; mt++) {
                float v00 = accG[mt][b_][0] + bi0, v01 = accG[mt][b_][1] + bi1;
                float v10 = accG[mt][b_][2] + bi0, v11 = accG[mt][b_][3] + bi1;
                v00 = fmaxf(v00, __shfl_xor_sync(0xffffffffu, v00, 4));
                v00 = fmaxf(v00, __shfl_xor_sync(0xffffffffu, v00, 8));
                v01 = fmaxf(v01, __shfl_xor_sync(0xffffffffu, v01, 4));
                v01 = fmaxf(v01, __shfl_xor_sync(0xffffffffu, v01, 8));
                v10 = fmaxf(v10, __shfl_xor_sync(0xffffffffu, v10, 4));
                v10 = fmaxf(v10, __shfl_xor_sync(0xffffffffu, v10, 8));
                v11 = fmaxf(v11, __shfl_xor_sync(0xffffffffu, v11, 4));
                v11 = fmaxf(v11, __shfl_xor_sync(0xffffffffu, v11, 8));
                if ((g & 3) == 0) {
                    int p01 = mt * 4 + (g >> 2), p23 = p01 + 2;
                    GX[i * 16 + p01]       = __float2half_rn(v00);
                    GX[(i + 1) * 16 + p01] = __float2half_rn(v01);
                    GX[i * 16 + p23]       = __float2half_rn(v10);
                    GX[(i + 1) * 16 + p23] = __float2half_rn(v11);
                }
            }
        }
    }
    __syncthreads();

    // ---- phase 3 (warps 0-3): f = theta @ phiP^T, softmax, y = a @ gx ----
    if (warp < 4) {
        float accF[2][4];
#pragma unroll
        for (int n_ = 0; n_ < 2; n_++)
#pragma unroll
            for (int c_ = 0; c_ < 4; c_++) accF[n_][c_] = 0.f;

        const __half* PHh = (const __half*)(smem + OFF_PH);
        for (int ks = 0; ks < 8; ks++) {
            uint32_t th[4];
            int r = warp * 16 + (lane & 15), ch = ks * 2 + (lane >> 4);
            ldm4(th, sbase + OFF_TH + r * 256 + ((ch ^ (r & 7)) << 4));
#pragma unroll
            for (int n_ = 0; n_ < 2; n_++) {
                int m = n_ * 8 + g;
                const uint32_t* bh = (const uint32_t*)(PHh + m * 136 + ks * 16 + t * 2);
                mma16816(accF[n_], th, bh[0], bh[4]);
            }
        }
        // softmax over 16 m-columns; rows: A = warp*16+g, B = +8
        float a0 = accF[0][0], a1 = accF[0][1], a2 = accF[1][0], a3 = accF[1][1];
        float c0 = accF[0][2], c1 = accF[0][3], c2 = accF[1][2], c3 = accF[1][3];
        float mA = hmax4(a0, a1, a2, a3), mB = hmax4(c0, c1, c2, c3);
        mA = fmaxf(mA, __shfl_xor_sync(0xffffffffu, mA, 1));
        mA = fmaxf(mA, __shfl_xor_sync(0xffffffffu, mA, 2));
        mB = fmaxf(mB, __shfl_xor_sync(0xffffffffu, mB, 1));
        mB = fmaxf(mB, __shfl_xor_sync(0xffffffffu, mB, 2));
        a0 = __expf(a0 - mA); a1 = __expf(a1 - mA); a2 = __expf(a2 - mA); a3 = __expf(a3 - mA);
        c0 = __expf(c0 - mB); c1 = __expf(c1 - mB); c2 = __expf(c2 - mB); c3 = __expf(c3 - mB);
        float sA = a0 + a1 + a2 + a3, sB = c0 + c1 + c2 + c3;
        sA += __shfl_xor_sync(0xffffffffu, sA, 1);
        sA += __shfl_xor_sync(0xffffffffu, sA, 2);
        sB += __shfl_xor_sync(0xffffffffu, sB, 1);
        sB += __shfl_xor_sync(0xffffffffu, sB, 2);
        float iA = 1.0f / sA, iB = 1.0f / sB;
        a0 *= iA; a1 *= iA; a2 *= iA; a3 *= iA;
        c0 *= iB; c1 *= iB; c2 *= iB; c3 *= iB;
        uint32_t fa[4];
        fa[0] = packh2(a0, a1); fa[1] = packh2(c0, c1);
        fa[2] = packh2(a2, a3); fa[3] = packh2(c2, c3);

        // y[64][128] = a[64][16] @ gxp  (K=16)
        float accY[16][4];
#pragma unroll
        for (int nt = 0; nt < 16; nt++)
#pragma unroll
            for (int c_ = 0; c_ < 4; c_++) accY[nt][c_] = 0.f;
        const __half* GX = (const __half*)(smem + OFF_GX);
#pragma unroll
        for (int nt = 0; nt < 16; nt++) {
            int irow = nt * 8 + g;
            const uint32_t* bp = (const uint32_t*)(GX + irow * 16 + t * 2);
            mma16816(accY[nt], fa, bp[0], bp[4]);
        }
        // store y fp16 swizzled
        uint32_t* YB = (uint32_t*)(smem + OFF_YB);
        int r0 = warp * 16 + g, r1 = r0 + 8;
#pragma unroll
        for (int nt = 0; nt < 16; nt++) {
            YB[r0 * 64 + (((nt ^ (r0 & 7)) << 2) | t)] = packh2(accY[nt][0], accY[nt][1]);
            YB[r1 * 64 + (((nt ^ (r1 & 7)) << 2) | t)] = packh2(accY[nt][2], accY[nt][3]);
        }
    }
    __syncthreads();

    // ---- phase 4: wy[64][256] = y @ Ww^T, + bias + fp32 residual, scatter ----
    float accW[4][4][4];
#pragma unroll
    for (int a_ = 0; a_ < 4; a_++)
#pragma unroll
        for (int b_ = 0; b_ < 4; b_++)
#pragma unroll
            for (int c_ = 0; c_ < 4; c_++) accW[a_][b_][c_] = 0.f;

    for (int ks = 0; ks < 8; ks++) {
        uint32_t ya[4][4];
        int rr = lane & 15, hk = lane >> 4;
#pragma unroll
        for (int mt = 0; mt < 4; mt++) {
            int r = mt * 16 + rr, ch = ks * 2 + hk;
            ldm4(ya[mt], sbase + OFF_YB + r * 256 + ((ch ^ (r & 7)) << 4));
        }
#pragma unroll
        for (int b_ = 0; b_ < 4; b_++) {
            int j = warp * 32 + b_ * 8 + g;  // output channel c
            const __half* p = g_Wwh + j * 128 + ks * 16 + t * 2;
            uint32_t w0 = *(const uint32_t*)p, w1 = *(const uint32_t*)(p + 8);
#pragma unroll
            for (int mt = 0; mt < 4; mt++) mma16816(accW[mt][b_], ya[mt], w0, w1);
        }
    }

    {
#pragma unroll
        for (int b_ = 0; b_ < 4; b_++) {
            int c = warp * 32 + b_ * 8 + t * 2;
            float bi0 = b2s[c], bi1 = b2s[c + 1];
#pragma unroll
            for (int mt = 0; mt < 4; mt++) {
#pragma unroll
                for (int h_ = 0; h_ < 2; h_++) {
                    int r = mt * 16 + g + h_ * 8;
                    const float2 xres = *(const float2*)(XF + r * XF_STRIDE + c);
                    float o0 = accW[mt][b_][h_ * 2 + 0] + bi0 + xres.x;
                    float o1 = accW[mt][b_][h_ * 2 + 1] + bi1 + xres.y;
                    float2* dst = (float2*)(out + ((size_t)blk * 64 + gos[r]) * 256 + c);
                    *dst = make_float2(o0, o1);
                }
            }
        }
    }
}

extern "C" void kernel_launch(void* const* d_in, const int* in_sizes, int n_in,
                              void* d_out, int out_size) {
    const float* x       = (const float*)d_in[0];
    const int*   grouped = (const int*)d_in[1];
    const float* tw  = (const float*)d_in[3];
    const float* tb  = (const float*)d_in[4];
    const float* pw  = (const float*)d_in[5];
    const float* pb  = (const float*)d_in[6];
    const float* gw  = (const float*)d_in[7];
    const float* gb  = (const float*)d_in[8];
    const float* ww  = (const float*)d_in[9];
    const float* wb  = (const float*)d_in[10];
    const float* gam = (const float*)d_in[11];
    const float* bet = (const float*)d_in[12];
    float* out = (float*)d_out;

    prep_kernel<<<384, 256>>>(tw, tb, pw, pb, gw, gb, ww, wb, gam, bet);
    cudaFuncSetAttribute(nl_kernel, cudaFuncAttributeMaxDynamicSharedMemorySize, SMEM_BYTES);
    nl_kernel<<<4096, 256, SMEM_BYTES>>>(x, grouped, out);
}